// round 6
// baseline (speedup 1.0000x reference)
#include <cuda_runtime.h>
#include <cuda_bf16.h>
#include <cstdint>

// ---------------------------------------------------------------------------
// mLSTM single step, B=8192, V=50257, E=1024, H=2048, O=2
//   x   = emb[inp]
//   m_t = (x@W_mx^T + b_mx) * (h0@W_mh^T + b_mh)
//   g_z = act(x@W_zx^T + b_zx + m_t@W_zm^T + b_zm)  f,i,o: sigmoid; c: tanh
//   cx  = f*c0 + i*c~ ; hx = o*tanh(cx) ; out = hx@W_dec^T + b_dec
// d_out: [ out(B,2) | hx(B,H) | cx(B,H) ]  fp32
//
// tcgen05 is unavailable (harness emits compute_103 PTX; tcgen05 is arch-'a'
// specific). So: mma.sync bf16 HMMA path, tuned for issue throughput:
//   - 512 threads / 16 warps per CTA (2x r4) -> 4 warps per SMSP
//   - warp subtile 32x16, all 4 gates per warp (acc = 64 regs, epilogue local)
//   - ldmatrix.x4 operand loads (3x fewer LDS instructions)
//   - cp.async 2-stage pipeline, BK=32
// ---------------------------------------------------------------------------

#define B_  8192
#define E_  1024
#define H_  2048
#define MEG (1 << 20)

__device__ __align__(16) __nv_bfloat16 g_xb [(size_t)B_ * E_];   // 16 MB
__device__ __align__(16) __nv_bfloat16 g_h0b[(size_t)B_ * H_];   // 32 MB
__device__ __align__(16) __nv_bfloat16 g_mtb[(size_t)B_ * H_];   // 32 MB
__device__ __align__(16) __nv_bfloat16 g_wb [(size_t)30 * MEG];  // 60 MB

#define OFF_MX 0
#define OFF_MH (2 * MEG)
#define OFF_ZX(z) (6 * MEG + (size_t)(z) * 6 * MEG)   // z: 0=f 1=i 2=o 3=c (HxE)
#define OFF_ZM(z) (8 * MEG + (size_t)(z) * 6 * MEG)   //                  (HxH)

// ---------------------------------------------------------------------------
// helpers
// ---------------------------------------------------------------------------
__device__ __forceinline__ uint32_t smem_u32(const void* p) {
    uint32_t a;
    asm("{ .reg .u64 t; cvta.to.shared.u64 t, %1; cvt.u32.u64 %0, t; }"
        : "=r"(a) : "l"(p));
    return a;
}
__device__ __forceinline__ void cpa16(uint32_t dst, const void* src) {
    asm volatile("cp.async.cg.shared.global [%0], [%1], 16;\n" :: "r"(dst), "l"(src));
}
__device__ __forceinline__ void cp_commit() { asm volatile("cp.async.commit_group;\n" ::); }
template <int N> __device__ __forceinline__ void cp_wait() {
    asm volatile("cp.async.wait_group %0;\n" :: "n"(N));
}
__device__ __forceinline__ void ldsm4(uint32_t& r0, uint32_t& r1, uint32_t& r2,
                                      uint32_t& r3, uint32_t addr) {
    asm volatile("ldmatrix.sync.aligned.m8n8.x4.shared.b16 {%0,%1,%2,%3}, [%4];"
                 : "=r"(r0), "=r"(r1), "=r"(r2), "=r"(r3) : "r"(addr));
}
__device__ __forceinline__ void mma16816(float c[4], const uint32_t a[4], const uint32_t b[2]) {
    asm volatile(
        "mma.sync.aligned.m16n8k16.row.col.f32.bf16.bf16.f32 "
        "{%0,%1,%2,%3}, {%4,%5,%6,%7}, {%8,%9}, {%0,%1,%2,%3};\n"
        : "+f"(c[0]), "+f"(c[1]), "+f"(c[2]), "+f"(c[3])
        : "r"(a[0]), "r"(a[1]), "r"(a[2]), "r"(a[3]), "r"(b[0]), "r"(b[1]));
}
__device__ __forceinline__ float sigf(float v)   { return 1.f / (1.f + __expf(-v)); }
__device__ __forceinline__ float tanhf_(float v) { return fmaf(2.f, 1.f / (1.f + __expf(-2.f * v)), -1.f); }

// ---------------------------------------------------------------------------
// fp32 -> bf16 conversion (weights + h0) and embedding gather
// ---------------------------------------------------------------------------
struct Cvt { const float* s[11]; __nv_bfloat16* d[11]; int n4[11]; };

__global__ void cvt_f32_bf16(Cvt a) {
    const int seg = blockIdx.y;
    const float4* __restrict__ s = (const float4*)a.s[seg];
    uint2* __restrict__ d = (uint2*)a.d[seg];
    const int n4 = a.n4[seg];
    for (int i = blockIdx.x * blockDim.x + threadIdx.x; i < n4;
         i += gridDim.x * blockDim.x) {
        float4 v = s[i];
        __nv_bfloat162 lo = __float22bfloat162_rn(make_float2(v.x, v.y));
        __nv_bfloat162 hi = __float22bfloat162_rn(make_float2(v.z, v.w));
        uint2 o; o.x = *(unsigned*)&lo; o.y = *(unsigned*)&hi;
        d[i] = o;
    }
}

__global__ void gather_x(const int* __restrict__ inp, const float* __restrict__ emb) {
    const int b = blockIdx.x;
    const int v = inp[b];
    float4 t = ((const float4*)(emb + (size_t)v * E_))[threadIdx.x];
    __nv_bfloat162 lo = __float22bfloat162_rn(make_float2(t.x, t.y));
    __nv_bfloat162 hi = __float22bfloat162_rn(make_float2(t.z, t.w));
    uint2 o; o.x = *(unsigned*)&lo; o.y = *(unsigned*)&hi;
    ((uint2*)(g_xb + (size_t)b * E_))[threadIdx.x] = o;
}

// ---------------------------------------------------------------------------
// Tile geometry: BM=128, BN=64, BK=32; LDS_=40 (pad, conflict-free ldmatrix)
// 512 threads, 16 warps: wm = warp&3 (row 32-block), wn = warp>>2 (col 16-block)
// ---------------------------------------------------------------------------
#define LDS_  40
#define NT_X  32     // K=1024 / 32
#define NT_TOT 96    // + K=2048 / 32

// ---------------------------------------------------------------------------
// gates kernel: 4 gate GEMMs fused; dynamic smem 62464 B
//   As 2x(128x40), Bs 2x4x(64x40) bf16, bias 4x64 f32
// ---------------------------------------------------------------------------
#define GATES_SMEM (61440 + 1024)

__global__ __launch_bounds__(512, 1)
void gemm_gates(const float* __restrict__ bfx, const float* __restrict__ bfm,
                const float* __restrict__ bix, const float* __restrict__ bim,
                const float* __restrict__ box_, const float* __restrict__ bom,
                const float* __restrict__ bcx, const float* __restrict__ bcm,
                const float* __restrict__ c0,
                float* __restrict__ hx, float* __restrict__ cx) {
    extern __shared__ __align__(16) __nv_bfloat16 sm[];
    auto As  = [&](int s)        { return sm + (size_t)s * (128 * LDS_); };
    auto Bsz = [&](int s, int z) { return sm + 10240 + (size_t)(s * 4 + z) * (64 * LDS_); };
    float* bs = (float*)(sm + 30720);

    const int m0 = blockIdx.y * 128;
    const int n0 = blockIdx.x * 64;
    const int tid = threadIdx.x, lane = tid & 31, warp = tid >> 5;
    const int wm = warp & 3, wn = warp >> 2;      // wn 0..3
    const int g = lane >> 2, ti = lane & 3;
    const int l16 = lane & 15, kh = lane >> 4;    // ldmatrix addressing

    if (tid < 64) {
        const int n = n0 + tid;
        bs[0 * 64 + tid] = bfx[n] + bfm[n];
        bs[1 * 64 + tid] = bix[n] + bim[n];
        bs[2 * 64 + tid] = box_[n] + bom[n];
        bs[3 * 64 + tid] = bcx[n] + bcm[n];
    }

    float acc[4][2][2][4];
#pragma unroll
    for (int z = 0; z < 4; z++)
#pragma unroll
        for (int mt = 0; mt < 2; mt++)
#pragma unroll
            for (int nt = 0; nt < 2; nt++)
#pragma unroll
                for (int j = 0; j < 4; j++) acc[z][mt][nt][j] = 0.f;

    auto issue = [&](int t, int s) {
        const __nv_bfloat16* Ab; int ld; int tt = t;
        const bool xph = (t < NT_X);
        if (xph) { Ab = g_xb;  ld = E_; }
        else     { Ab = g_mtb; ld = H_; tt = t - NT_X; }
        const int k0 = tt * 32;
        {   // A: 128x32, 512 lds -> 1/thread
            int r = tid >> 2, c = tid & 3;
            cpa16(smem_u32(As(s) + r * LDS_ + c * 8),
                  Ab + (size_t)(m0 + r) * ld + k0 + c * 8);
        }
#pragma unroll
        for (int i = 0; i < 2; i++) {   // B: 4x64x32 -> 2/thread
            int lin = tid + i * 512;
            int z = lin >> 8, rr = (lin >> 2) & 63, cc = lin & 3;
            const __nv_bfloat16* Wb = g_wb + (xph ? OFF_ZX(z) : OFF_ZM(z));
            cpa16(smem_u32(Bsz(s, z) + rr * LDS_ + cc * 8),
                  Wb + (size_t)(n0 + rr) * ld + k0 + cc * 8);
        }
        cp_commit();
    };

    issue(0, 0);
    for (int t = 0; t < NT_TOT; t++) {
        if (t + 1 < NT_TOT) { issue(t + 1, (t + 1) & 1); cp_wait<1>(); }
        else                { cp_wait<0>(); }
        __syncthreads();
        const int st = t & 1;
#pragma unroll
        for (int ks = 0; ks < 2; ks++) {
            const int kb = ks * 16;
            uint32_t af[2][4];
#pragma unroll
            for (int mt = 0; mt < 2; mt++)   // A 16x16 per ldmatrix.x4
                ldsm4(af[mt][0], af[mt][1], af[mt][2], af[mt][3],
                      smem_u32(As(st) + (wm * 32 + mt * 16 + l16) * LDS_ + kb + kh * 8));
#pragma unroll
            for (int z = 0; z < 4; z++) {
                uint32_t r0, r1, r2, r3;     // B 16n x 16k per ldmatrix.x4
                ldsm4(r0, r1, r2, r3,
                      smem_u32(Bsz(st, z) + (wn * 16 + l16) * LDS_ + kb + kh * 8));
                uint32_t b0[2] = {r0, r2}, b1[2] = {r1, r3};
#pragma unroll
                for (int mt = 0; mt < 2; mt++) {
                    mma16816(acc[z][mt][0], af[mt], b0);
                    mma16816(acc[z][mt][1], af[mt], b1);
                }
            }
        }
        __syncthreads();
    }

    // epilogue: all 4 gates are warp-local -> cx, hx
#pragma unroll
    for (int mt = 0; mt < 2; mt++)
#pragma unroll
        for (int nt = 0; nt < 2; nt++) {
            const int nl = wn * 16 + nt * 8 + ti * 2;
            const int n = n0 + nl;
#pragma unroll
            for (int h = 0; h < 2; h++) {
                const int m = m0 + wm * 32 + mt * 16 + g + h * 8;
                float2 c0v = *(const float2*)(c0 + (size_t)m * H_ + n);
                float2 hv, cvv;
#pragma unroll
                for (int j = 0; j < 2; j++) {
                    const int e = h * 2 + j;
                    float fg = sigf(acc[0][mt][nt][e] + bs[0 * 64 + nl + j]);
                    float ig = sigf(acc[1][mt][nt][e] + bs[1 * 64 + nl + j]);
                    float og = sigf(acc[2][mt][nt][e] + bs[2 * 64 + nl + j]);
                    float ct = tanhf_(acc[3][mt][nt][e] + bs[3 * 64 + nl + j]);
                    float c0e = j ? c0v.y : c0v.x;
                    float cv = fg * c0e + ig * ct;
                    ((float*)&cvv)[j] = cv;
                    ((float*)&hv)[j]  = og * tanhf_(cv);
                }
                *(float2*)(cx + (size_t)m * H_ + n) = cvv;
                *(float2*)(hx + (size_t)m * H_ + n) = hv;
            }
        }
}

// ---------------------------------------------------------------------------
// m_t kernel: dual accumulators (x-part, h-part); static smem ~31.5 KB
// ---------------------------------------------------------------------------
__global__ __launch_bounds__(512, 1)
void gemm_mt(const float* __restrict__ b_mx, const float* __restrict__ b_mh) {
    __shared__ __align__(16) __nv_bfloat16 As[2][128 * LDS_];
    __shared__ __align__(16) __nv_bfloat16 Bs[2][64 * LDS_];
    __shared__ float bs[2][64];

    const int m0 = blockIdx.y * 128;
    const int n0 = blockIdx.x * 64;
    const int tid = threadIdx.x, lane = tid & 31, warp = tid >> 5;
    const int wm = warp & 3, wn = warp >> 2;
    const int g = lane >> 2, ti = lane & 3;
    const int l16 = lane & 15, kh = lane >> 4;

    if (tid < 64) {
        bs[0][tid] = b_mx[n0 + tid];
        bs[1][tid] = b_mh[n0 + tid];
    }

    float ax[2][2][4], ah[2][2][4];
#pragma unroll
    for (int mt = 0; mt < 2; mt++)
#pragma unroll
        for (int nt = 0; nt < 2; nt++)
#pragma unroll
            for (int j = 0; j < 4; j++) { ax[mt][nt][j] = 0.f; ah[mt][nt][j] = 0.f; }

    auto issue = [&](int t, int s) {
        const __nv_bfloat16 *Ab, *Wb; int ld; int tt = t;
        if (t < NT_X) { Ab = g_xb;  Wb = g_wb + OFF_MX; ld = E_; }
        else          { Ab = g_h0b; Wb = g_wb + OFF_MH; ld = H_; tt = t - NT_X; }
        const int k0 = tt * 32;
        {
            int r = tid >> 2, c = tid & 3;
            cpa16(smem_u32(&As[s][r * LDS_ + c * 8]),
                  Ab + (size_t)(m0 + r) * ld + k0 + c * 8);
        }
        if (tid < 256) {
            int r = tid >> 2, c = tid & 3;
            cpa16(smem_u32(&Bs[s][r * LDS_ + c * 8]),
                  Wb + (size_t)(n0 + r) * ld + k0 + c * 8);
        }
        cp_commit();
    };

    issue(0, 0);
    for (int t = 0; t < NT_TOT; t++) {
        if (t + 1 < NT_TOT) { issue(t + 1, (t + 1) & 1); cp_wait<1>(); }
        else                { cp_wait<0>(); }
        __syncthreads();
        const int st = t & 1;
        const bool px = (t < NT_X);
#pragma unroll
        for (int ks = 0; ks < 2; ks++) {
            const int kb = ks * 16;
            uint32_t af[2][4];
#pragma unroll
            for (int mt = 0; mt < 2; mt++)
                ldsm4(af[mt][0], af[mt][1], af[mt][2], af[mt][3],
                      smem_u32(&As[st][(wm * 32 + mt * 16 + l16) * LDS_ + kb + kh * 8]));
            uint32_t r0, r1, r2, r3;
            ldsm4(r0, r1, r2, r3,
                  smem_u32(&Bs[st][(wn * 16 + l16) * LDS_ + kb + kh * 8]));
            uint32_t b0[2] = {r0, r2}, b1[2] = {r1, r3};
            if (px) {
#pragma unroll
                for (int mt = 0; mt < 2; mt++) {
                    mma16816(ax[mt][0], af[mt], b0);
                    mma16816(ax[mt][1], af[mt], b1);
                }
            } else {
#pragma unroll
                for (int mt = 0; mt < 2; mt++) {
                    mma16816(ah[mt][0], af[mt], b0);
                    mma16816(ah[mt][1], af[mt], b1);
                }
            }
        }
        __syncthreads();
    }

    // epilogue: m_t = (ax + b_mx) * (ah + b_mh)  -> bf16
#pragma unroll
    for (int mt = 0; mt < 2; mt++)
#pragma unroll
        for (int nt = 0; nt < 2; nt++) {
            const int nl = wn * 16 + nt * 8 + ti * 2;
            const int n = n0 + nl;
#pragma unroll
            for (int h = 0; h < 2; h++) {
                const int m = m0 + wm * 32 + mt * 16 + g + h * 8;
                float v0 = (ax[mt][nt][h * 2 + 0] + bs[0][nl + 0]) *
                           (ah[mt][nt][h * 2 + 0] + bs[1][nl + 0]);
                float v1 = (ax[mt][nt][h * 2 + 1] + bs[0][nl + 1]) *
                           (ah[mt][nt][h * 2 + 1] + bs[1][nl + 1]);
                __nv_bfloat162 p = __float22bfloat162_rn(make_float2(v0, v1));
                *(unsigned*)(g_mtb + (size_t)m * H_ + n) = *(unsigned*)&p;
            }
        }
}

// ---------------------------------------------------------------------------
// decoder: out[b,0:2] = hx[b]@W_dec^T + b_dec   (warp per row)
// ---------------------------------------------------------------------------
__global__ void decoder(const float* __restrict__ hx, const float* __restrict__ Wd,
                        const float* __restrict__ bd, float* __restrict__ out) {
    const int gw = (blockIdx.x * blockDim.x + threadIdx.x) >> 5;
    const int lane = threadIdx.x & 31;
    if (gw >= B_) return;
    const float4* h4 = (const float4*)(hx + (size_t)gw * H_);
    const float4* w0 = (const float4*)(Wd);
    const float4* w1 = (const float4*)(Wd + H_);
    float s0 = 0.f, s1 = 0.f;
    for (int i = lane; i < H_ / 4; i += 32) {
        float4 h = h4[i], a = w0[i], b = w1[i];
        s0 += h.x * a.x + h.y * a.y + h.z * a.z + h.w * a.w;
        s1 += h.x * b.x + h.y * b.y + h.z * b.z + h.w * b.w;
    }
#pragma unroll
    for (int o = 16; o; o >>= 1) {
        s0 += __shfl_xor_sync(0xFFFFFFFFu, s0, o);
        s1 += __shfl_xor_sync(0xFFFFFFFFu, s1, o);
    }
    if (lane == 0) {
        out[(size_t)gw * 2 + 0] = s0 + bd[0];
        out[(size_t)gw * 2 + 1] = s1 + bd[1];
    }
}

// ---------------------------------------------------------------------------
extern "C" void kernel_launch(void* const* d_in, const int* in_sizes, int n_in,
                              void* d_out, int out_size) {
    const int*   inp  = (const int*)  d_in[0];
    const float* h0   = (const float*)d_in[1];
    const float* c0   = (const float*)d_in[2];
    const float* emb  = (const float*)d_in[3];
    const float *W_mx = (const float*)d_in[4],  *b_mx = (const float*)d_in[5];
    const float *W_mh = (const float*)d_in[6],  *b_mh = (const float*)d_in[7];
    const float *W_fx = (const float*)d_in[8],  *b_fx = (const float*)d_in[9];
    const float *W_fm = (const float*)d_in[10], *b_fm = (const float*)d_in[11];
    const float *W_ix = (const float*)d_in[12], *b_ix = (const float*)d_in[13];
    const float *W_im = (const float*)d_in[14], *b_im = (const float*)d_in[15];
    const float *W_ox = (const float*)d_in[16], *b_ox = (const float*)d_in[17];
    const float *W_om = (const float*)d_in[18], *b_om = (const float*)d_in[19];
    const float *W_cx = (const float*)d_in[20], *b_cx = (const float*)d_in[21];
    const float *W_cm = (const float*)d_in[22], *b_cm = (const float*)d_in[23];
    const float *W_dec= (const float*)d_in[24], *b_dec= (const float*)d_in[25];
    float* out = (float*)d_out;

    __nv_bfloat16 *wb, *h0b;
    cudaGetSymbolAddress((void**)&wb,  g_wb);
    cudaGetSymbolAddress((void**)&h0b, g_h0b);

    // 1) convert weights + h0 to bf16
    Cvt cv;
    const float* srcs[11] = {W_mx, W_mh, W_fx, W_fm, W_ix, W_im, W_ox, W_om, W_cx, W_cm, h0};
    const size_t offs[11] = {OFF_MX, OFF_MH,
                             OFF_ZX(0), OFF_ZM(0), OFF_ZX(1), OFF_ZM(1),
                             OFF_ZX(2), OFF_ZM(2), OFF_ZX(3), OFF_ZM(3), 0};
    const int cnts[11] = {2*MEG, 4*MEG, 2*MEG, 4*MEG, 2*MEG, 4*MEG,
                          2*MEG, 4*MEG, 2*MEG, 4*MEG, 16*MEG};
    for (int i = 0; i < 11; i++) {
        cv.s[i]  = srcs[i];
        cv.d[i]  = (i == 10) ? h0b : (wb + offs[i]);
        cv.n4[i] = cnts[i] / 4;
    }
    cvt_f32_bf16<<<dim3(1024, 11), 256>>>(cv);

    // 2) x = bf16(emb[inp])
    gather_x<<<B_, 256>>>(inp, emb);

    // 3) m_t
    gemm_mt<<<dim3(H_ / 64, B_ / 128), 512>>>(b_mx, b_mh);

    // 4) gates + cx/hx fused, into d_out
    float* hx_out = out + 2 * (size_t)B_;
    float* cx_out = hx_out + (size_t)B_ * H_;
    cudaFuncSetAttribute(gemm_gates, cudaFuncAttributeMaxDynamicSharedMemorySize,
                         GATES_SMEM);
    gemm_gates<<<dim3(H_ / 64, B_ / 128), 512, GATES_SMEM>>>(
        b_fx, b_fm, b_ix, b_im, b_ox, b_om, b_cx, b_cm, c0, hx_out, cx_out);

    // 5) out = hx@W_dec^T + b_dec
    decoder<<<(B_ * 32) / 256, 256>>>(hx_out, W_dec, b_dec, out);
}